// round 1
// baseline (speedup 1.0000x reference)
#include <cuda_runtime.h>

#define KB 16
#define KC 512
#define KCI 256
#define KN 1024

// ---------------- scratch (no allocs allowed -> __device__ globals) ----------
__device__ float g_re[KB * KCI * KN];              // 16 MB  rgb embed  [b][i][n]
__device__ float g_fe[KB * KCI * KN];              // 16 MB  flow embed [b][i][n]
__device__ float g_S[(size_t)KB * KN * KN];        // 64 MB  scores     [b][n][m]
__device__ float g_rmax[KB * KN];
__device__ float g_rsum[KB * KN];
__device__ float g_cmax[KB * KN];
__device__ float g_csum[KB * KN];
__device__ float g_ry[KB * KCI * KN];              // 16 MB  rgb_y  [b][i][n]
__device__ float g_fy[KB * KCI * KN];              // 16 MB  flow_y [b][i][m]
__device__ float g_t[2 * (size_t)KB * KC * KN];    // 64 MB  conv2 out, rgb then flow
__device__ float g_mean[2 * KC];
__device__ float g_rstd[2 * KC];

// =============================================================================
// embed: E[b,i,n] = bias[i] + sum_c W[i,c] * X[b,c,n]     (E = sel ? g_fe : g_re)
// 64x64 tile, BK=16, 256 threads, 4x4 micro-tile
// =============================================================================
__global__ __launch_bounds__(256) void embed_kernel(
    const float* __restrict__ X, const float* __restrict__ W,
    const float* __restrict__ bias, int sel) {
  float* E = sel ? g_fe : g_re;
  int b = blockIdx.z;
  int i0 = blockIdx.y * 64, n0 = blockIdx.x * 64;
  __shared__ float Ws[16][65];
  __shared__ float Xs[16][65];
  int tid = threadIdx.x;
  int tx = tid & 15, ty = tid >> 4;
  const float* Xb = X + (size_t)b * KC * KN;
  float acc[4][4] = {};
  for (int c0 = 0; c0 < KC; c0 += 16) {
#pragma unroll
    for (int t = 0; t < 4; t++) {
      int idx = tid + 256 * t;
      int k = idx & 15, i = idx >> 4;
      Ws[k][i] = W[(size_t)(i0 + i) * KC + c0 + k];
    }
#pragma unroll
    for (int t = 0; t < 4; t++) {
      int idx = tid + 256 * t;
      int n = idx & 63, k = idx >> 6;
      Xs[k][n] = Xb[(size_t)(c0 + k) * KN + n0 + n];
    }
    __syncthreads();
#pragma unroll
    for (int k = 0; k < 16; k++) {
      float a[4], bb[4];
#pragma unroll
      for (int u = 0; u < 4; u++) a[u] = Ws[k][ty + 16 * u];
#pragma unroll
      for (int v = 0; v < 4; v++) bb[v] = Xs[k][tx + 16 * v];
#pragma unroll
      for (int u = 0; u < 4; u++)
#pragma unroll
        for (int v = 0; v < 4; v++) acc[u][v] += a[u] * bb[v];
    }
    __syncthreads();
  }
  float* Eb = E + (size_t)b * KCI * KN;
#pragma unroll
  for (int u = 0; u < 4; u++) {
    int i = i0 + ty + 16 * u;
    float bi = bias[i];
#pragma unroll
    for (int v = 0; v < 4; v++)
      Eb[(size_t)i * KN + n0 + tx + 16 * v] = acc[u][v] + bi;
  }
}

// =============================================================================
// scores: S[b,n,m] = sum_i re[b,i,n] * fe[b,i,m]
// =============================================================================
__global__ __launch_bounds__(256) void scores_kernel() {
  int b = blockIdx.z;
  int n0 = blockIdx.y * 64, m0 = blockIdx.x * 64;
  __shared__ float As[16][65];  // As[k][n]
  __shared__ float Bs[16][65];  // Bs[k][m]
  const float* REb = g_re + (size_t)b * KCI * KN;
  const float* FEb = g_fe + (size_t)b * KCI * KN;
  int tid = threadIdx.x;
  int tx = tid & 15, ty = tid >> 4;
  float acc[4][4] = {};
  for (int i0 = 0; i0 < KCI; i0 += 16) {
#pragma unroll
    for (int t = 0; t < 4; t++) {
      int idx = tid + 256 * t;
      int n = idx & 63, k = idx >> 6;
      As[k][n] = REb[(size_t)(i0 + k) * KN + n0 + n];
    }
#pragma unroll
    for (int t = 0; t < 4; t++) {
      int idx = tid + 256 * t;
      int m = idx & 63, k = idx >> 6;
      Bs[k][m] = FEb[(size_t)(i0 + k) * KN + m0 + m];
    }
    __syncthreads();
#pragma unroll
    for (int k = 0; k < 16; k++) {
      float a[4], bb[4];
#pragma unroll
      for (int u = 0; u < 4; u++) a[u] = As[k][ty + 16 * u];
#pragma unroll
      for (int v = 0; v < 4; v++) bb[v] = Bs[k][tx + 16 * v];
#pragma unroll
      for (int u = 0; u < 4; u++)
#pragma unroll
        for (int v = 0; v < 4; v++) acc[u][v] += a[u] * bb[v];
    }
    __syncthreads();
  }
  float* Sb = g_S + (size_t)b * KN * KN;
#pragma unroll
  for (int u = 0; u < 4; u++)
#pragma unroll
    for (int v = 0; v < 4; v++)
      Sb[(size_t)(n0 + ty + 16 * u) * KN + m0 + tx + 16 * v] = acc[u][v];
}

// =============================================================================
// row stats: per (b,n): max_m and sum_m exp(S - max)
// =============================================================================
__global__ __launch_bounds__(256) void rowstats_kernel() {
  int bn = blockIdx.x;
  const float* row = g_S + (size_t)bn * KN;
  int tid = threadIdx.x;
  float v[4];
  float m = -1e30f;
#pragma unroll
  for (int t = 0; t < 4; t++) {
    v[t] = row[tid + 256 * t];
    m = fmaxf(m, v[t]);
  }
  __shared__ float sh[256];
  sh[tid] = m;
  __syncthreads();
  for (int s = 128; s > 0; s >>= 1) {
    if (tid < s) sh[tid] = fmaxf(sh[tid], sh[tid + s]);
    __syncthreads();
  }
  m = sh[0];
  __syncthreads();
  float s0 = 0.f;
#pragma unroll
  for (int t = 0; t < 4; t++) s0 += __expf(v[t] - m);
  sh[tid] = s0;
  __syncthreads();
  for (int s = 128; s > 0; s >>= 1) {
    if (tid < s) sh[tid] += sh[tid + s];
    __syncthreads();
  }
  if (tid == 0) {
    g_rmax[bn] = m;
    g_rsum[bn] = sh[0];
  }
}

// =============================================================================
// col stats: per (b,m): max_n and sum_n exp(S - max).  threads (32 m, 8 n-slices)
// =============================================================================
__global__ __launch_bounds__(256) void colstats_kernel() {
  int b = blockIdx.y;
  int m = blockIdx.x * 32 + threadIdx.x;
  int ty = threadIdx.y;
  const float* Sb = g_S + (size_t)b * KN * KN;
  float mx = -1e30f;
  for (int n = ty; n < KN; n += 8) mx = fmaxf(mx, Sb[(size_t)n * KN + m]);
  __shared__ float shm[8][32];
  shm[ty][threadIdx.x] = mx;
  __syncthreads();
  if (ty == 0) {
    float r = shm[0][threadIdx.x];
#pragma unroll
    for (int j = 1; j < 8; j++) r = fmaxf(r, shm[j][threadIdx.x]);
    shm[0][threadIdx.x] = r;
  }
  __syncthreads();
  mx = shm[0][threadIdx.x];
  __syncthreads();
  float s = 0.f;
  for (int n = ty; n < KN; n += 8) s += __expf(Sb[(size_t)n * KN + m] - mx);
  shm[ty][threadIdx.x] = s;
  __syncthreads();
  if (ty == 0) {
    float r = 0.f;
#pragma unroll
    for (int j = 0; j < 8; j++) r += shm[j][threadIdx.x];
    g_cmax[b * KN + m] = mx;
    g_csum[b * KN + m] = r;
  }
}

// =============================================================================
// rgb_y[b,i,n] = (1/rsum[b,n]) * sum_m exp(S[b,n,m]-rmax[b,n]) * fe[b,i,m]
// =============================================================================
__global__ __launch_bounds__(256) void rgby_kernel() {
  int b = blockIdx.z;
  int i0 = blockIdx.y * 64, n0 = blockIdx.x * 64;
  const float* Sb = g_S + (size_t)b * KN * KN;
  const float* FEb = g_fe + (size_t)b * KCI * KN;
  __shared__ float Fs[16][65];  // Fs[km][i]
  __shared__ float Ps[16][65];  // Ps[km][n]
  __shared__ float rmx[64];
  int tid = threadIdx.x;
  int tx = tid & 15, ty = tid >> 4;
  if (tid < 64) rmx[tid] = g_rmax[b * KN + n0 + tid];
  __syncthreads();
  float acc[4][4] = {};
  for (int m0 = 0; m0 < KN; m0 += 16) {
#pragma unroll
    for (int t = 0; t < 4; t++) {
      int idx = tid + 256 * t;
      int k = idx & 15, i = idx >> 4;
      Fs[k][i] = FEb[(size_t)(i0 + i) * KN + m0 + k];
    }
#pragma unroll
    for (int t = 0; t < 4; t++) {
      int idx = tid + 256 * t;
      int k = idx & 15, n = idx >> 4;
      Ps[k][n] = __expf(Sb[(size_t)(n0 + n) * KN + m0 + k] - rmx[n]);
    }
    __syncthreads();
#pragma unroll
    for (int k = 0; k < 16; k++) {
      float a[4], p[4];
#pragma unroll
      for (int u = 0; u < 4; u++) a[u] = Fs[k][ty + 16 * u];
#pragma unroll
      for (int v = 0; v < 4; v++) p[v] = Ps[k][tx + 16 * v];
#pragma unroll
      for (int u = 0; u < 4; u++)
#pragma unroll
        for (int v = 0; v < 4; v++) acc[u][v] += a[u] * p[v];
    }
    __syncthreads();
  }
  float* Yb = g_ry + (size_t)b * KCI * KN;
#pragma unroll
  for (int v = 0; v < 4; v++) {
    int n = n0 + tx + 16 * v;
    float inv = 1.0f / g_rsum[b * KN + n];
#pragma unroll
    for (int u = 0; u < 4; u++)
      Yb[(size_t)(i0 + ty + 16 * u) * KN + n] = acc[u][v] * inv;
  }
}

// =============================================================================
// flow_y[b,i,m] = (1/csum[b,m]) * sum_n exp(S[b,n,m]-cmax[b,m]) * re[b,i,n]
// =============================================================================
__global__ __launch_bounds__(256) void flowy_kernel() {
  int b = blockIdx.z;
  int i0 = blockIdx.y * 64, m0 = blockIdx.x * 64;
  const float* Sb = g_S + (size_t)b * KN * KN;
  const float* REb = g_re + (size_t)b * KCI * KN;
  __shared__ float Rs[16][65];  // Rs[kn][i]
  __shared__ float Ps[16][65];  // Ps[kn][m]
  __shared__ float cmx[64];
  int tid = threadIdx.x;
  int tx = tid & 15, ty = tid >> 4;
  if (tid < 64) cmx[tid] = g_cmax[b * KN + m0 + tid];
  __syncthreads();
  float acc[4][4] = {};
  for (int n0 = 0; n0 < KN; n0 += 16) {
#pragma unroll
    for (int t = 0; t < 4; t++) {
      int idx = tid + 256 * t;
      int k = idx & 15, i = idx >> 4;
      Rs[k][i] = REb[(size_t)(i0 + i) * KN + n0 + k];
    }
#pragma unroll
    for (int t = 0; t < 4; t++) {
      int idx = tid + 256 * t;
      int m = idx & 63, k = idx >> 6;
      Ps[k][m] = __expf(Sb[(size_t)(n0 + k) * KN + m0 + m] - cmx[m]);
    }
    __syncthreads();
#pragma unroll
    for (int k = 0; k < 16; k++) {
      float a[4], p[4];
#pragma unroll
      for (int u = 0; u < 4; u++) a[u] = Rs[k][ty + 16 * u];
#pragma unroll
      for (int v = 0; v < 4; v++) p[v] = Ps[k][tx + 16 * v];
#pragma unroll
      for (int u = 0; u < 4; u++)
#pragma unroll
        for (int v = 0; v < 4; v++) acc[u][v] += a[u] * p[v];
    }
    __syncthreads();
  }
  float* Yb = g_fy + (size_t)b * KCI * KN;
#pragma unroll
  for (int v = 0; v < 4; v++) {
    int m = m0 + tx + 16 * v;
    float inv = 1.0f / g_csum[b * KN + m];
#pragma unroll
    for (int u = 0; u < 4; u++)
      Yb[(size_t)(i0 + ty + 16 * u) * KN + m] = acc[u][v] * inv;
  }
}

// =============================================================================
// conv2: T[b,c,n] = bw[c] + sum_i W[c,i] * Y[b,i,n]   (Y = sel?g_fy:g_ry)
// =============================================================================
__global__ __launch_bounds__(256) void conv2_kernel(
    const float* __restrict__ W, const float* __restrict__ bias, int sel) {
  const float* Y = sel ? g_fy : g_ry;
  float* T = g_t + (size_t)sel * KB * KC * KN;
  int b = blockIdx.z;
  int c0 = blockIdx.y * 64, n0 = blockIdx.x * 64;
  __shared__ float Ws[16][65];
  __shared__ float Ys[16][65];
  int tid = threadIdx.x;
  int tx = tid & 15, ty = tid >> 4;
  const float* Yb = Y + (size_t)b * KCI * KN;
  float acc[4][4] = {};
  for (int i0 = 0; i0 < KCI; i0 += 16) {
#pragma unroll
    for (int t = 0; t < 4; t++) {
      int idx = tid + 256 * t;
      int k = idx & 15, c = idx >> 4;
      Ws[k][c] = W[(size_t)(c0 + c) * KCI + i0 + k];
    }
#pragma unroll
    for (int t = 0; t < 4; t++) {
      int idx = tid + 256 * t;
      int n = idx & 63, k = idx >> 6;
      Ys[k][n] = Yb[(size_t)(i0 + k) * KN + n0 + n];
    }
    __syncthreads();
#pragma unroll
    for (int k = 0; k < 16; k++) {
      float a[4], bb[4];
#pragma unroll
      for (int u = 0; u < 4; u++) a[u] = Ws[k][ty + 16 * u];
#pragma unroll
      for (int v = 0; v < 4; v++) bb[v] = Ys[k][tx + 16 * v];
#pragma unroll
      for (int u = 0; u < 4; u++)
#pragma unroll
        for (int v = 0; v < 4; v++) acc[u][v] += a[u] * bb[v];
    }
    __syncthreads();
  }
  float* Tb = T + (size_t)b * KC * KN;
#pragma unroll
  for (int u = 0; u < 4; u++) {
    int c = c0 + ty + 16 * u;
    float bi = bias[c];
#pragma unroll
    for (int v = 0; v < 4; v++)
      Tb[(size_t)c * KN + n0 + tx + 16 * v] = acc[u][v] + bi;
  }
}

// =============================================================================
// BN stats (training mode): per channel c over (B, N): mean, rstd
// grid (KC, 2), 256 threads
// =============================================================================
__global__ __launch_bounds__(256) void bnstats_kernel() {
  int c = blockIdx.x;
  int sel = blockIdx.y;
  const float* T = g_t + (size_t)sel * KB * KC * KN;
  int tid = threadIdx.x;
  float s = 0.f, s2 = 0.f;
  for (int b = 0; b < KB; b++) {
    const float* p = T + ((size_t)b * KC + c) * KN;
    for (int n = tid; n < KN; n += 256) {
      float v = p[n];
      s += v;
      s2 += v * v;
    }
  }
  __shared__ float sh1[256], sh2[256];
  sh1[tid] = s;
  sh2[tid] = s2;
  __syncthreads();
  for (int st = 128; st > 0; st >>= 1) {
    if (tid < st) {
      sh1[tid] += sh1[tid + st];
      sh2[tid] += sh2[tid + st];
    }
    __syncthreads();
  }
  if (tid == 0) {
    float m = sh1[0] / (float)(KB * KN);
    float var = sh2[0] / (float)(KB * KN) - m * m;
    g_mean[sel * KC + c] = m;
    g_rstd[sel * KC + c] = rsqrtf(var + 1e-5f);
  }
}

// =============================================================================
// finalize: Z = (T - mean)*rstd*gamma + beta + X
// =============================================================================
__global__ __launch_bounds__(256) void finalize_kernel(
    const float* __restrict__ X, const float* __restrict__ gamma,
    const float* __restrict__ beta, float* __restrict__ Z, int sel) {
  size_t idx = (size_t)blockIdx.x * 256 + threadIdx.x;
  const float* T = g_t + (size_t)sel * KB * KC * KN;
  int c = (int)((idx >> 10) & (KC - 1));
  float m = g_mean[sel * KC + c];
  float r = g_rstd[sel * KC + c];
  Z[idx] = (T[idx] - m) * r * gamma[c] + beta[c] + X[idx];
}

// =============================================================================
extern "C" void kernel_launch(void* const* d_in, const int* in_sizes, int n_in,
                              void* d_out, int out_size) {
  const float* rgb        = (const float*)d_in[0];
  const float* flow       = (const float*)d_in[1];
  const float* wg_rgb     = (const float*)d_in[2];
  const float* bg_rgb     = (const float*)d_in[3];
  const float* wg_flow    = (const float*)d_in[4];
  const float* bg_flow    = (const float*)d_in[5];
  const float* ww_rgb     = (const float*)d_in[6];
  const float* bw_rgb     = (const float*)d_in[7];
  const float* gamma_rgb  = (const float*)d_in[8];
  const float* beta_rgb   = (const float*)d_in[9];
  const float* ww_flow    = (const float*)d_in[10];
  const float* bw_flow    = (const float*)d_in[11];
  const float* gamma_flow = (const float*)d_in[12];
  const float* beta_flow  = (const float*)d_in[13];
  float* out = (float*)d_out;

  dim3 thr(256);
  embed_kernel<<<dim3(KN / 64, KCI / 64, KB), thr>>>(rgb, wg_rgb, bg_rgb, 0);
  embed_kernel<<<dim3(KN / 64, KCI / 64, KB), thr>>>(flow, wg_flow, bg_flow, 1);
  scores_kernel<<<dim3(KN / 64, KN / 64, KB), thr>>>();
  rowstats_kernel<<<KB * KN, thr>>>();
  colstats_kernel<<<dim3(KN / 32, KB), dim3(32, 8)>>>();
  rgby_kernel<<<dim3(KN / 64, KCI / 64, KB), thr>>>();
  flowy_kernel<<<dim3(KN / 64, KCI / 64, KB), thr>>>();
  conv2_kernel<<<dim3(KN / 64, KC / 64, KB), thr>>>(ww_rgb, bw_rgb, 0);
  conv2_kernel<<<dim3(KN / 64, KC / 64, KB), thr>>>(ww_flow, bw_flow, 1);
  bnstats_kernel<<<dim3(KC, 2), thr>>>();
  finalize_kernel<<<(KB * KC * KN) / 256, thr>>>(rgb, gamma_rgb, beta_rgb, out, 0);
  finalize_kernel<<<(KB * KC * KN) / 256, thr>>>(
      flow, gamma_flow, beta_flow, out + (size_t)KB * KC * KN, 1);
}

// round 3
// speedup vs baseline: 2.3180x; 2.3180x over previous
#include <cuda_runtime.h>
#include <cuda_bf16.h>
#include <cstdint>

#define KB 16
#define KC 512
#define KCI 256
#define KN 1024

// ---------------- scratch (no allocs allowed -> __device__ globals) ----------
__device__ float g_rgbT[(size_t)KB * KN * KC];   // [b][n][c]
__device__ float g_flowT[(size_t)KB * KN * KC];
__device__ float g_re[(size_t)KB * KCI * KN];    // [b][i][n]
__device__ float g_fe[(size_t)KB * KCI * KN];
__device__ float g_reT[(size_t)KB * KN * KCI];   // [b][n][i]
__device__ float g_feT[(size_t)KB * KN * KCI];
__device__ float g_S[(size_t)KB * KN * KN];      // [b][n][m]
__device__ float g_S2[(size_t)KB * KN * KN];     // [b][m][n] = S^T
__device__ float g_rmax[KB * KN];
__device__ float g_rsum[KB * KN];
__device__ float g_cmax[KB * KN];
__device__ float g_csum[KB * KN];
__device__ float g_yrT[(size_t)KB * KN * KCI];   // rgb_y^T [b][n][i]
__device__ float g_yfT[(size_t)KB * KN * KCI];   // flow_y^T [b][m][i]
__device__ float g_t[2 * (size_t)KB * KC * KN];  // conv2 out
__device__ float g_mean[2 * KC];
__device__ float g_rstd[2 * KC];

// ============================ helpers ========================================
__device__ __forceinline__ uint32_t smem_u32(const void* p) {
  uint32_t a;
  asm("{ .reg .u64 t; cvta.to.shared.u64 t, %1; cvt.u32.u64 %0, t; }"
      : "=r"(a) : "l"(p));
  return a;
}

__device__ __forceinline__ void ldm_x4(uint32_t addr, uint32_t& r0,
                                       uint32_t& r1, uint32_t& r2,
                                       uint32_t& r3) {
  asm volatile(
      "ldmatrix.sync.aligned.m8n8.x4.shared.b16 {%0,%1,%2,%3}, [%4];"
      : "=r"(r0), "=r"(r1), "=r"(r2), "=r"(r3) : "r"(addr));
}

__device__ __forceinline__ void mma_bf16(float* d, const uint32_t* a,
                                         const uint32_t* b) {
  asm volatile(
      "mma.sync.aligned.m16n8k16.row.col.f32.bf16.bf16.f32 "
      "{%0,%1,%2,%3}, {%4,%5,%6,%7}, {%8,%9}, {%0,%1,%2,%3};"
      : "+f"(d[0]), "+f"(d[1]), "+f"(d[2]), "+f"(d[3])
      : "r"(a[0]), "r"(a[1]), "r"(a[2]), "r"(a[3]), "r"(b[0]), "r"(b[1]));
}

// swizzled byte offset within a 128B-row tile
__device__ __forceinline__ uint32_t sw_off(int row, int cb) {
  uint32_t off = (uint32_t)(row * 128 + cb);
  return off ^ ((off >> 3) & 0x70);
}

// split fp32x4 -> bf16 hi/lo, store 8B each to swizzled tiles
__device__ __forceinline__ void split_sts(char* hi, char* lo, int r, int q,
                                          float4 v) {
  __nv_bfloat162 h01 = __floats2bfloat162_rn(v.x, v.y);
  __nv_bfloat162 h23 = __floats2bfloat162_rn(v.z, v.w);
  __nv_bfloat162 l01 = __floats2bfloat162_rn(v.x - __low2float(h01),
                                             v.y - __high2float(h01));
  __nv_bfloat162 l23 = __floats2bfloat162_rn(v.z - __low2float(h23),
                                             v.w - __high2float(h23));
  uint32_t off = sw_off(r, q * 8);
  uint2 hp, lp;
  hp.x = *(uint32_t*)&h01; hp.y = *(uint32_t*)&h23;
  lp.x = *(uint32_t*)&l01; lp.y = *(uint32_t*)&l23;
  *(uint2*)(hi + off) = hp;
  *(uint2*)(lo + off) = lp;
}

// smem layout (within 1024-aligned dynamic smem)
#define OFF_AHI 0
#define OFF_ALO 16384
#define OFF_BHI 32768
#define OFF_BLO 40960
#define OFF_MX  49152
#define OFF_INV 49408
#define SMEM_DYN (49664 + 1024)

// =============================================================================
// Tensor-core GEMM block (HMMA mma.sync): out tile [128 rows][64 cols].
//   D[r][c] = sum_k A[r][k] * B'[c][k],  B'[c][k] = mx? exp(B[c][k]-mx[c]) : B
//   v = D * (sumv ? 1/sumv[c] : 1) + (bias ? bias[r] : 0)
//   -> outN [r][c] and/or outT [c][r], both coalesced via smem.
// =============================================================================
__global__ __launch_bounds__(256, 2) void gemm_tc(
    const float* __restrict__ A, unsigned long long sA, int lda,
    const float* __restrict__ Bp, unsigned long long sB, int ldb,
    const float* __restrict__ mx, const float* __restrict__ sumv,
    const float* __restrict__ bias,
    float* __restrict__ outN, unsigned long long soN, int ldoN,
    float* __restrict__ outT, unsigned long long soT, int ldoT, int K) {
  extern __shared__ char s_dyn[];
  char* sb = (char*)(((uintptr_t)s_dyn + 1023) & ~(uintptr_t)1023);
  char* sAhi = sb + OFF_AHI;
  char* sAlo = sb + OFF_ALO;
  char* sBhi = sb + OFF_BHI;
  char* sBlo = sb + OFF_BLO;
  float* s_mx = (float*)(sb + OFF_MX);
  float* s_inv = (float*)(sb + OFF_INV);
  float* s_f32 = (float*)sb;  // epilogue reuse [128][65]

  uint32_t uAhi = smem_u32(sAhi), uAlo = smem_u32(sAlo);
  uint32_t uBhi = smem_u32(sBhi), uBlo = smem_u32(sBlo);

  int tid = threadIdx.x;
  int wid = tid >> 5, lane = tid & 31;
  int wr = wid & 3, wc = wid >> 2;  // warp 32x32 tile at (wr*32, wc*32)
  int b = blockIdx.z;
  int i0 = blockIdx.y * 128;
  int n0 = blockIdx.x * 64;

  if (tid < 64) {
    if (mx) s_mx[tid] = mx[b * KN + n0 + tid];
    if (sumv) s_inv[tid] = 1.0f / sumv[b * KN + n0 + tid];
  }

  const float* Ab = A + (size_t)b * sA;
  const float* Bb = Bp + (size_t)b * sB;

  // ldmatrix per-lane address selectors
  int aRow = lane & 15, aCb = (lane >> 4) * 16;          // A 16x16 tile
  int bRow = ((lane >> 4) & 1) * 8 + (lane & 7);         // B 16x16 (n x k)
  int bCb = ((lane >> 3) & 1) * 16;

  float acc[2][4][4];
#pragma unroll
  for (int mi = 0; mi < 2; mi++)
#pragma unroll
    for (int ni = 0; ni < 4; ni++)
#pragma unroll
      for (int e = 0; e < 4; e++) acc[mi][ni][e] = 0.f;

  int NC = K >> 6;
  __syncthreads();  // s_mx/s_inv visible
  for (int ch = 0; ch < NC; ch++) {
    int k0 = ch << 6;
    float4 aR[8], bR[4];
#pragma unroll
    for (int t = 0; t < 8; t++) {
      int idx = tid + (t << 8);
      aR[t] = *(const float4*)(Ab + (size_t)(i0 + (idx >> 4)) * lda + k0 +
                               ((idx & 15) << 2));
    }
#pragma unroll
    for (int t = 0; t < 4; t++) {
      int idx = tid + (t << 8);
      bR[t] = *(const float4*)(Bb + (size_t)(n0 + (idx >> 4)) * ldb + k0 +
                               ((idx & 15) << 2));
    }
    if (mx) {
#pragma unroll
      for (int t = 0; t < 4; t++) {
        float m_ = s_mx[(tid + (t << 8)) >> 4];
        bR[t].x = __expf(bR[t].x - m_);
        bR[t].y = __expf(bR[t].y - m_);
        bR[t].z = __expf(bR[t].z - m_);
        bR[t].w = __expf(bR[t].w - m_);
      }
    }
    if (ch) __syncthreads();  // prior chunk's MMA reads done
#pragma unroll
    for (int t = 0; t < 8; t++) {
      int idx = tid + (t << 8);
      split_sts(sAhi, sAlo, idx >> 4, idx & 15, aR[t]);
    }
#pragma unroll
    for (int t = 0; t < 4; t++) {
      int idx = tid + (t << 8);
      split_sts(sBhi, sBlo, idx >> 4, idx & 15, bR[t]);
    }
    __syncthreads();

#pragma unroll
    for (int ks = 0; ks < 4; ks++) {
      int kb = ks * 32;
      uint32_t ah[2][4], al[2][4], bh[2][4], bl[2][4];
#pragma unroll
      for (int mi = 0; mi < 2; mi++) {
        int r = wr * 32 + mi * 16 + aRow;
        uint32_t o = sw_off(r, kb + aCb);
        ldm_x4(uAhi + o, ah[mi][0], ah[mi][1], ah[mi][2], ah[mi][3]);
        ldm_x4(uAlo + o, al[mi][0], al[mi][1], al[mi][2], al[mi][3]);
      }
#pragma unroll
      for (int ng = 0; ng < 2; ng++) {
        int r = wc * 32 + ng * 16 + bRow;
        uint32_t o = sw_off(r, kb + bCb);
        ldm_x4(uBhi + o, bh[ng][0], bh[ng][1], bh[ng][2], bh[ng][3]);
        ldm_x4(uBlo + o, bl[ng][0], bl[ng][1], bl[ng][2], bl[ng][3]);
      }
#pragma unroll
      for (int mi = 0; mi < 2; mi++)
#pragma unroll
        for (int ni = 0; ni < 4; ni++) {
          float* d = acc[mi][ni];
          const uint32_t* bhp = &bh[ni >> 1][(ni & 1) * 2];
          const uint32_t* blp = &bl[ni >> 1][(ni & 1) * 2];
          mma_bf16(d, ah[mi], bhp);
          mma_bf16(d, ah[mi], blp);
          mma_bf16(d, al[mi], bhp);
        }
    }
  }
  __syncthreads();

  // --------------------------- epilogue --------------------------------------
#pragma unroll
  for (int mi = 0; mi < 2; mi++) {
    int rl = wr * 32 + mi * 16 + (lane >> 2);
    float bv0 = bias ? __ldg(bias + i0 + rl) : 0.f;
    float bv1 = bias ? __ldg(bias + i0 + rl + 8) : 0.f;
#pragma unroll
    for (int ni = 0; ni < 4; ni++) {
      int c = wc * 32 + ni * 8 + 2 * (lane & 3);
      float s0 = sumv ? s_inv[c] : 1.f;
      float s1 = sumv ? s_inv[c + 1] : 1.f;
      s_f32[rl * 65 + c] = acc[mi][ni][0] * s0 + bv0;
      s_f32[rl * 65 + c + 1] = acc[mi][ni][1] * s1 + bv0;
      s_f32[(rl + 8) * 65 + c] = acc[mi][ni][2] * s0 + bv1;
      s_f32[(rl + 8) * 65 + c + 1] = acc[mi][ni][3] * s1 + bv1;
    }
  }
  __syncthreads();

  if (outN) {
    float* on = outN + (size_t)b * soN;
#pragma unroll
    for (int t = 0; t < 8; t++) {
      int idx = tid + (t << 8);   // over 2048 float4s
      int rr = idx >> 4, q = idx & 15;
      float4 v;
      v.x = s_f32[rr * 65 + q * 4 + 0];
      v.y = s_f32[rr * 65 + q * 4 + 1];
      v.z = s_f32[rr * 65 + q * 4 + 2];
      v.w = s_f32[rr * 65 + q * 4 + 3];
      *(float4*)(on + (size_t)(i0 + rr) * ldoN + n0 + (q << 2)) = v;
    }
  }
  if (outT) {
    float* ot = outT + (size_t)b * soT;
#pragma unroll
    for (int t = 0; t < 32; t++) {
      int idx = tid + (t << 8);  // 8192 scalars
      int c = idx >> 7, rr = idx & 127;
      ot[(size_t)(n0 + c) * ldoT + i0 + rr] = s_f32[rr * 65 + c];
    }
  }
}

// =============================================================================
// transpose: per batch [C][N] -> [N][C]
// =============================================================================
__global__ __launch_bounds__(256) void transpose_kernel(
    const float* __restrict__ in, float* __restrict__ out) {
  __shared__ float t[32][33];
  int b = blockIdx.z;
  const float* ib = in + (size_t)b * KC * KN;
  float* ob = out + (size_t)b * KC * KN;
  int n0 = blockIdx.x * 32, c0 = blockIdx.y * 32;
  int x = threadIdx.x, y = threadIdx.y;
#pragma unroll
  for (int j = 0; j < 4; j++)
    t[y + 8 * j][x] = ib[(size_t)(c0 + y + 8 * j) * KN + n0 + x];
  __syncthreads();
#pragma unroll
  for (int j = 0; j < 4; j++)
    ob[(size_t)(n0 + y + 8 * j) * KC + c0 + x] = t[x][y + 8 * j];
}

// =============================================================================
// row stats: per (b,row): max and sum(exp(x-max)) over last axis (1024)
// =============================================================================
__global__ __launch_bounds__(256) void rowstats_kernel(
    const float* __restrict__ S, float* __restrict__ omax,
    float* __restrict__ osum) {
  int bn = blockIdx.x;
  const float* row = S + (size_t)bn * KN;
  int tid = threadIdx.x;
  float4 v = *(const float4*)(row + tid * 4);
  float m = fmaxf(fmaxf(v.x, v.y), fmaxf(v.z, v.w));
  __shared__ float sh[256];
  sh[tid] = m;
  __syncthreads();
  for (int s = 128; s > 0; s >>= 1) {
    if (tid < s) sh[tid] = fmaxf(sh[tid], sh[tid + s]);
    __syncthreads();
  }
  m = sh[0];
  __syncthreads();
  float s0 = __expf(v.x - m) + __expf(v.y - m) + __expf(v.z - m) +
             __expf(v.w - m);
  sh[tid] = s0;
  __syncthreads();
  for (int s = 128; s > 0; s >>= 1) {
    if (tid < s) sh[tid] += sh[tid + s];
    __syncthreads();
  }
  if (tid == 0) {
    omax[bn] = m;
    osum[bn] = sh[0];
  }
}

// =============================================================================
// BN stats per channel over (B,N)
// =============================================================================
__global__ __launch_bounds__(256) void bnstats_kernel() {
  int c = blockIdx.x;
  int sel = blockIdx.y;
  const float* T = g_t + (size_t)sel * KB * KC * KN;
  int tid = threadIdx.x;
  float s = 0.f, s2 = 0.f;
  for (int b = 0; b < KB; b++) {
    const float* p = T + ((size_t)b * KC + c) * KN;
    for (int n = tid; n < KN; n += 256) {
      float v = p[n];
      s += v;
      s2 += v * v;
    }
  }
  __shared__ float sh1[256], sh2[256];
  sh1[tid] = s;
  sh2[tid] = s2;
  __syncthreads();
  for (int st = 128; st > 0; st >>= 1) {
    if (tid < st) {
      sh1[tid] += sh1[tid + st];
      sh2[tid] += sh2[tid + st];
    }
    __syncthreads();
  }
  if (tid == 0) {
    float m = sh1[0] / (float)(KB * KN);
    float var = sh2[0] / (float)(KB * KN) - m * m;
    g_mean[sel * KC + c] = m;
    g_rstd[sel * KC + c] = rsqrtf(var + 1e-5f);
  }
}

// =============================================================================
// finalize: Z = (T - mean)*rstd*gamma + beta + X
// =============================================================================
__global__ __launch_bounds__(256) void finalize_kernel(
    const float* __restrict__ X, const float* __restrict__ gamma,
    const float* __restrict__ beta, float* __restrict__ Z, int sel) {
  size_t idx = (size_t)blockIdx.x * 256 + threadIdx.x;
  const float* T = g_t + (size_t)sel * KB * KC * KN;
  int c = (int)((idx >> 10) & (KC - 1));
  float m = g_mean[sel * KC + c];
  float r = g_rstd[sel * KC + c];
  Z[idx] = (T[idx] - m) * r * gamma[c] + beta[c] + X[idx];
}

// =============================================================================
extern "C" void kernel_launch(void* const* d_in, const int* in_sizes, int n_in,
                              void* d_out, int out_size) {
  const float* rgb        = (const float*)d_in[0];
  const float* flow       = (const float*)d_in[1];
  const float* wg_rgb     = (const float*)d_in[2];
  const float* bg_rgb     = (const float*)d_in[3];
  const float* wg_flow    = (const float*)d_in[4];
  const float* bg_flow    = (const float*)d_in[5];
  const float* ww_rgb     = (const float*)d_in[6];
  const float* bw_rgb     = (const float*)d_in[7];
  const float* gamma_rgb  = (const float*)d_in[8];
  const float* beta_rgb   = (const float*)d_in[9];
  const float* ww_flow    = (const float*)d_in[10];
  const float* bw_flow    = (const float*)d_in[11];
  const float* gamma_flow = (const float*)d_in[12];
  const float* beta_flow  = (const float*)d_in[13];
  float* out = (float*)d_out;

  float *p_rgbT, *p_flowT, *p_re, *p_fe, *p_reT, *p_feT, *p_S, *p_S2;
  float *p_rmax, *p_rsum, *p_cmax, *p_csum, *p_yrT, *p_yfT, *p_t;
  cudaGetSymbolAddress((void**)&p_rgbT, g_rgbT);
  cudaGetSymbolAddress((void**)&p_flowT, g_flowT);
  cudaGetSymbolAddress((void**)&p_re, g_re);
  cudaGetSymbolAddress((void**)&p_fe, g_fe);
  cudaGetSymbolAddress((void**)&p_reT, g_reT);
  cudaGetSymbolAddress((void**)&p_feT, g_feT);
  cudaGetSymbolAddress((void**)&p_S, g_S);
  cudaGetSymbolAddress((void**)&p_S2, g_S2);
  cudaGetSymbolAddress((void**)&p_rmax, g_rmax);
  cudaGetSymbolAddress((void**)&p_rsum, g_rsum);
  cudaGetSymbolAddress((void**)&p_cmax, g_cmax);
  cudaGetSymbolAddress((void**)&p_csum, g_csum);
  cudaGetSymbolAddress((void**)&p_yrT, g_yrT);
  cudaGetSymbolAddress((void**)&p_yfT, g_yfT);
  cudaGetSymbolAddress((void**)&p_t, g_t);

  cudaFuncSetAttribute(gemm_tc, cudaFuncAttributeMaxDynamicSharedMemorySize,
                       SMEM_DYN);

  dim3 thr(256);

  // 1) input transposes: [c][n] -> [n][c]
  transpose_kernel<<<dim3(KN / 32, KC / 32, KB), dim3(32, 8)>>>(rgb, p_rgbT);
  transpose_kernel<<<dim3(KN / 32, KC / 32, KB), dim3(32, 8)>>>(flow, p_flowT);

  // 2) embeds: E[i][n] = W @ XT^T ; write normal + transposed
  gemm_tc<<<dim3(16, 2, KB), thr, SMEM_DYN>>>(
      wg_rgb, 0ull, KC, p_rgbT, (unsigned long long)KN * KC, KC,
      nullptr, nullptr, bg_rgb,
      p_re, (unsigned long long)KCI * KN, KN,
      p_reT, (unsigned long long)KN * KCI, KCI, KC);
  gemm_tc<<<dim3(16, 2, KB), thr, SMEM_DYN>>>(
      wg_flow, 0ull, KC, p_flowT, (unsigned long long)KN * KC, KC,
      nullptr, nullptr, bg_flow,
      p_fe, (unsigned long long)KCI * KN, KN,
      p_feT, (unsigned long long)KN * KCI, KCI, KC);

  // 3) scores S[n][m] = reT @ feT^T  and  S2[m][n] = feT @ reT^T (= S^T)
  gemm_tc<<<dim3(16, 8, KB), thr, SMEM_DYN>>>(
      p_reT, (unsigned long long)KN * KCI, KCI,
      p_feT, (unsigned long long)KN * KCI, KCI,
      nullptr, nullptr, nullptr,
      p_S, (unsigned long long)KN * KN, KN, nullptr, 0ull, 0, KCI);
  gemm_tc<<<dim3(16, 8, KB), thr, SMEM_DYN>>>(
      p_feT, (unsigned long long)KN * KCI, KCI,
      p_reT, (unsigned long long)KN * KCI, KCI,
      nullptr, nullptr, nullptr,
      p_S2, (unsigned long long)KN * KN, KN, nullptr, 0ull, 0, KCI);

  // 4) softmax stats (row-wise on S and on S2)
  rowstats_kernel<<<KB * KN, thr>>>(p_S, p_rmax, p_rsum);
  rowstats_kernel<<<KB * KN, thr>>>(p_S2, p_cmax, p_csum);

  // 5) attention applies (exp fused into B staging, 1/sum in epilogue)
  gemm_tc<<<dim3(16, 2, KB), thr, SMEM_DYN>>>(
      p_fe, (unsigned long long)KCI * KN, KN,
      p_S, (unsigned long long)KN * KN, KN,
      p_rmax, p_rsum, nullptr,
      nullptr, 0ull, 0, p_yrT, (unsigned long long)KN * KCI, KCI, KN);
  gemm_tc<<<dim3(16, 2, KB), thr, SMEM_DYN>>>(
      p_re, (unsigned long long)KCI * KN, KN,
      p_S2, (unsigned long long)KN * KN, KN,
      p_cmax, p_csum, nullptr,
      nullptr, 0ull, 0, p_yfT, (unsigned long long)KN * KCI, KCI, KN);

  // 6) conv2: T[c][n] = W @ YT^T + bias
  gemm_tc<<<dim3(16, 4, KB), thr, SMEM_DYN>>>(
      ww_rgb, 0ull, KCI, p_yrT, (unsigned long long)KN * KCI, KCI,
      nullptr, nullptr, bw_rgb,
      p_t, (unsigned long long)KC * KN, KN, nullptr, 0ull, 0, KCI);
  gemm_tc<<<dim3(16, 4, KB), thr, SMEM_DYN>>>(
      ww_flow, 0ull, KCI, p_yfT, (unsigned long long)KN * KCI, KCI,
      nullptr, nullptr, bw_flow,
      p_t + (size_t)KB * KC * KN, (unsigned long long)KC * KN, KN,
      nullptr, 0ull, 0, KCI);

  // 7) BN + residual
  bnstats_kernel<<<dim3(KC, 2), thr>>>();
  finalize_kernel<<<(KB * KC * KN) / 256, thr>>>(rgb, gamma_rgb, beta_rgb,
                                                 out, 0);
  finalize_kernel<<<(KB * KC * KN) / 256, thr>>>(
      flow, gamma_flow, beta_flow, out + (size_t)KB * KC * KN, 1);
}

// round 5
// speedup vs baseline: 2.3400x; 1.0095x over previous
#include <cuda_runtime.h>
#include <cuda_bf16.h>
#include <cstdint>

#define KB 16
#define KC 512
#define KCI 256
#define KN 1024

// ---------------- scratch (no allocs allowed -> __device__ globals) ----------
__device__ float g_rgbT[(size_t)KB * KN * KC];   // [b][n][c]
__device__ float g_flowT[(size_t)KB * KN * KC];
__device__ float g_re[(size_t)KB * KCI * KN];    // [b][i][n]
__device__ float g_fe[(size_t)KB * KCI * KN];
__device__ float g_reT[(size_t)KB * KN * KCI];   // [b][n][i]
__device__ float g_feT[(size_t)KB * KN * KCI];
__device__ float g_S[(size_t)KB * KN * KN];      // [b][n][m]
__device__ float g_S2[(size_t)KB * KN * KN];     // [b][m][n] = S^T
__device__ float g_rmax[KB * KN];
__device__ float g_rsum[KB * KN];
__device__ float g_cmax[KB * KN];
__device__ float g_csum[KB * KN];
__device__ float g_yrT[(size_t)KB * KN * KCI];   // rgb_y^T [b][n][i]
__device__ float g_yfT[(size_t)KB * KN * KCI];   // flow_y^T [b][m][i]
__device__ float g_t[2 * (size_t)KB * KC * KN];  // conv2 out
__device__ float g_mean[2 * KC];
__device__ float g_rstd[2 * KC];
// softmax partials: rows (16 m-blocks), cols (8 n-blocks)
__device__ float g_prm[KB * KN * 16];
__device__ float g_prs[KB * KN * 16];
__device__ float g_pcm[KB * KN * 8];
__device__ float g_pcs[KB * KN * 8];
// BN partials: [sel][c][b][xb]
__device__ float g_pbs[2 * KC * KB * 16];
__device__ float g_pbs2[2 * KC * KB * 16];

// ============================ helpers ========================================
__device__ __forceinline__ uint32_t smem_u32(const void* p) {
  uint32_t a;
  asm("{ .reg .u64 t; cvta.to.shared.u64 t, %1; cvt.u32.u64 %0, t; }"
      : "=r"(a) : "l"(p));
  return a;
}

__device__ __forceinline__ void ldm_x4(uint32_t addr, uint32_t& r0,
                                       uint32_t& r1, uint32_t& r2,
                                       uint32_t& r3) {
  asm volatile(
      "ldmatrix.sync.aligned.m8n8.x4.shared.b16 {%0,%1,%2,%3}, [%4];"
      : "=r"(r0), "=r"(r1), "=r"(r2), "=r"(r3) : "r"(addr));
}

__device__ __forceinline__ void mma_bf16(float* d, const uint32_t* a,
                                         const uint32_t* b) {
  asm volatile(
      "mma.sync.aligned.m16n8k16.row.col.f32.bf16.bf16.f32 "
      "{%0,%1,%2,%3}, {%4,%5,%6,%7}, {%8,%9}, {%0,%1,%2,%3};"
      : "+f"(d[0]), "+f"(d[1]), "+f"(d[2]), "+f"(d[3])
      : "r"(a[0]), "r"(a[1]), "r"(a[2]), "r"(a[3]), "r"(b[0]), "r"(b[1]));
}

__device__ __forceinline__ uint32_t sw_off(int row, int cb) {
  uint32_t off = (uint32_t)(row * 128 + cb);
  return off ^ ((off >> 3) & 0x70);
}

__device__ __forceinline__ void split_sts(char* hi, char* lo, int r, int q,
                                          float4 v) {
  __nv_bfloat162 h01 = __floats2bfloat162_rn(v.x, v.y);
  __nv_bfloat162 h23 = __floats2bfloat162_rn(v.z, v.w);
  __nv_bfloat162 l01 = __floats2bfloat162_rn(v.x - __low2float(h01),
                                             v.y - __high2float(h01));
  __nv_bfloat162 l23 = __floats2bfloat162_rn(v.z - __low2float(h23),
                                             v.w - __high2float(h23));
  uint32_t off = sw_off(r, q * 8);
  uint2 hp, lp;
  hp.x = *(uint32_t*)&h01; hp.y = *(uint32_t*)&h23;
  lp.x = *(uint32_t*)&l01; lp.y = *(uint32_t*)&l23;
  *(uint2*)(hi + off) = hp;
  *(uint2*)(lo + off) = lp;
}

// smem: double-buffered tiles, 48KB per buffer
#define BUF_STRIDE 49152
#define OFF_AHI 0
#define OFF_ALO 16384
#define OFF_BHI 32768
#define OFF_BLO 40960
#define OFF_MX  98304
#define OFF_INV 98560
#define SMEM_DYN (98816 + 1024)

// =============================================================================
// HMMA GEMM block: out tile [128 rows][64 cols], double-buffered K pipeline.
//   D[r][c] = sum_k A[r][k] * B'[c][k],  B'[c][k] = mx? exp(B[c][k]-mx[c]) : B
//   v = D * (sumv ? 1/sumv[c] : 1) + (bias ? bias[r] : 0)
// Optional epilogue emitters: outN[r][c], outT[c][r], softmax partials
// (row over cols / col over rows), BN partial sums per row.
// =============================================================================
__global__ __launch_bounds__(256, 2) void gemm_tc(
    const float* __restrict__ A, unsigned long long sA, int lda,
    const float* __restrict__ Bp, unsigned long long sB, int ldb,
    const float* __restrict__ mx, const float* __restrict__ sumv,
    const float* __restrict__ bias,
    float* __restrict__ outN, unsigned long long soN, int ldoN,
    float* __restrict__ outT, unsigned long long soT, int ldoT,
    float* __restrict__ prm, float* __restrict__ prs,
    float* __restrict__ pcm, float* __restrict__ pcs,
    float* __restrict__ pbs, float* __restrict__ pbs2, int K) {
  extern __shared__ char s_dyn[];
  char* sb = (char*)(((uintptr_t)s_dyn + 1023) & ~(uintptr_t)1023);
  float* s_mx = (float*)(sb + OFF_MX);
  float* s_inv = (float*)(sb + OFF_INV);
  float* s_f32 = (float*)sb;  // epilogue reuse [128][65]

  uint32_t uAhi[2], uAlo[2], uBhi[2], uBlo[2];
  char *pAhi[2], *pAlo[2], *pBhi[2], *pBlo[2];
#pragma unroll
  for (int k = 0; k < 2; k++) {
    pAhi[k] = sb + k * BUF_STRIDE + OFF_AHI;
    pAlo[k] = sb + k * BUF_STRIDE + OFF_ALO;
    pBhi[k] = sb + k * BUF_STRIDE + OFF_BHI;
    pBlo[k] = sb + k * BUF_STRIDE + OFF_BLO;
    uAhi[k] = smem_u32(pAhi[k]);
    uAlo[k] = smem_u32(pAlo[k]);
    uBhi[k] = smem_u32(pBhi[k]);
    uBlo[k] = smem_u32(pBlo[k]);
  }

  int tid = threadIdx.x;
  int wid = tid >> 5, lane = tid & 31;
  int wr = wid & 3, wc = wid >> 2;
  int b = blockIdx.z;
  int i0 = blockIdx.y * 128;
  int n0 = blockIdx.x * 64;

  if (tid < 64) {
    if (mx) s_mx[tid] = mx[b * KN + n0 + tid];
    if (sumv) s_inv[tid] = 1.0f / sumv[b * KN + n0 + tid];
  }

  const float* Ab = A + (size_t)b * sA;
  const float* Bb = Bp + (size_t)b * sB;

  int aRow = lane & 15, aCb = (lane >> 4) * 16;
  int bRow = ((lane >> 4) & 1) * 8 + (lane & 7);
  int bCb = ((lane >> 3) & 1) * 16;

  float acc[2][4][4];
#pragma unroll
  for (int mi = 0; mi < 2; mi++)
#pragma unroll
    for (int ni = 0; ni < 4; ni++)
#pragma unroll
      for (int e = 0; e < 4; e++) acc[mi][ni][e] = 0.f;

  int NC = K >> 6;
  float4 aR[8], bR[4];
  // ---- prologue: chunk 0 -> buf0
#pragma unroll
  for (int t = 0; t < 8; t++) {
    int idx = tid + (t << 8);
    aR[t] = *(const float4*)(Ab + (size_t)(i0 + (idx >> 4)) * lda +
                             ((idx & 15) << 2));
  }
#pragma unroll
  for (int t = 0; t < 4; t++) {
    int idx = tid + (t << 8);
    bR[t] = *(const float4*)(Bb + (size_t)(n0 + (idx >> 4)) * ldb +
                             ((idx & 15) << 2));
  }
  __syncthreads();  // s_mx/s_inv visible to ALL threads before any exp use
  if (mx) {
#pragma unroll
    for (int t = 0; t < 4; t++) {
      float m_ = s_mx[(tid + (t << 8)) >> 4];
      bR[t].x = __expf(bR[t].x - m_);
      bR[t].y = __expf(bR[t].y - m_);
      bR[t].z = __expf(bR[t].z - m_);
      bR[t].w = __expf(bR[t].w - m_);
    }
  }
#pragma unroll
  for (int t = 0; t < 8; t++) {
    int idx = tid + (t << 8);
    split_sts(pAhi[0], pAlo[0], idx >> 4, idx & 15, aR[t]);
  }
#pragma unroll
  for (int t = 0; t < 4; t++) {
    int idx = tid + (t << 8);
    split_sts(pBhi[0], pBlo[0], idx >> 4, idx & 15, bR[t]);
  }
  __syncthreads();

  for (int ch = 0; ch < NC; ch++) {
    int cur = ch & 1;
    bool hn = (ch + 1) < NC;
    if (hn) {
      int k0 = (ch + 1) << 6;
#pragma unroll
      for (int t = 0; t < 8; t++) {
        int idx = tid + (t << 8);
        aR[t] = *(const float4*)(Ab + (size_t)(i0 + (idx >> 4)) * lda + k0 +
                                 ((idx & 15) << 2));
      }
#pragma unroll
      for (int t = 0; t < 4; t++) {
        int idx = tid + (t << 8);
        bR[t] = *(const float4*)(Bb + (size_t)(n0 + (idx >> 4)) * ldb + k0 +
                                 ((idx & 15) << 2));
      }
    }
    // ---- MMA on buffer cur
#pragma unroll
    for (int ks = 0; ks < 4; ks++) {
      int kb = ks * 32;
      uint32_t ah[2][4], al[2][4], bh[2][4], bl[2][4];
#pragma unroll
      for (int mi = 0; mi < 2; mi++) {
        int r = wr * 32 + mi * 16 + aRow;
        uint32_t o = sw_off(r, kb + aCb);
        ldm_x4(uAhi[cur] + o, ah[mi][0], ah[mi][1], ah[mi][2], ah[mi][3]);
        ldm_x4(uAlo[cur] + o, al[mi][0], al[mi][1], al[mi][2], al[mi][3]);
      }
#pragma unroll
      for (int ng = 0; ng < 2; ng++) {
        int r = wc * 32 + ng * 16 + bRow;
        uint32_t o = sw_off(r, kb + bCb);
        ldm_x4(uBhi[cur] + o, bh[ng][0], bh[ng][1], bh[ng][2], bh[ng][3]);
        ldm_x4(uBlo[cur] + o, bl[ng][0], bl[ng][1], bl[ng][2], bl[ng][3]);
      }
#pragma unroll
      for (int mi = 0; mi < 2; mi++)
#pragma unroll
        for (int ni = 0; ni < 4; ni++) {
          float* d = acc[mi][ni];
          const uint32_t* bhp = &bh[ni >> 1][(ni & 1) * 2];
          const uint32_t* blp = &bl[ni >> 1][(ni & 1) * 2];
          mma_bf16(d, ah[mi], bhp);
          mma_bf16(d, ah[mi], blp);
          mma_bf16(d, al[mi], bhp);
        }
    }
    if (hn) {
      if (mx) {
#pragma unroll
        for (int t = 0; t < 4; t++) {
          float m_ = s_mx[(tid + (t << 8)) >> 4];
          bR[t].x = __expf(bR[t].x - m_);
          bR[t].y = __expf(bR[t].y - m_);
          bR[t].z = __expf(bR[t].z - m_);
          bR[t].w = __expf(bR[t].w - m_);
        }
      }
      int nxt = cur ^ 1;
#pragma unroll
      for (int t = 0; t < 8; t++) {
        int idx = tid + (t << 8);
        split_sts(pAhi[nxt], pAlo[nxt], idx >> 4, idx & 15, aR[t]);
      }
#pragma unroll
      for (int t = 0; t < 4; t++) {
        int idx = tid + (t << 8);
        split_sts(pBhi[nxt], pBlo[nxt], idx >> 4, idx & 15, bR[t]);
      }
    }
    __syncthreads();
  }

  // --------------------------- epilogue --------------------------------------
#pragma unroll
  for (int mi = 0; mi < 2; mi++) {
    int rl = wr * 32 + mi * 16 + (lane >> 2);
    float bv0 = bias ? __ldg(bias + i0 + rl) : 0.f;
    float bv1 = bias ? __ldg(bias + i0 + rl + 8) : 0.f;
#pragma unroll
    for (int ni = 0; ni < 4; ni++) {
      int c = wc * 32 + ni * 8 + 2 * (lane & 3);
      float s0 = sumv ? s_inv[c] : 1.f;
      float s1 = sumv ? s_inv[c + 1] : 1.f;
      s_f32[rl * 65 + c] = acc[mi][ni][0] * s0 + bv0;
      s_f32[rl * 65 + c + 1] = acc[mi][ni][1] * s1 + bv0;
      s_f32[(rl + 8) * 65 + c] = acc[mi][ni][2] * s0 + bv1;
      s_f32[(rl + 8) * 65 + c + 1] = acc[mi][ni][3] * s1 + bv1;
    }
  }
  __syncthreads();

  if (outN) {
    float* on = outN + (size_t)b * soN;
#pragma unroll
    for (int t = 0; t < 8; t++) {
      int idx = tid + (t << 8);
      int rr = idx >> 4, q = idx & 15;
      float4 v;
      v.x = s_f32[rr * 65 + q * 4 + 0];
      v.y = s_f32[rr * 65 + q * 4 + 1];
      v.z = s_f32[rr * 65 + q * 4 + 2];
      v.w = s_f32[rr * 65 + q * 4 + 3];
      *(float4*)(on + (size_t)(i0 + rr) * ldoN + n0 + (q << 2)) = v;
    }
  }
  if (outT) {
    float* ot = outT + (size_t)b * soT;
#pragma unroll
    for (int t = 0; t < 32; t++) {
      int idx = tid + (t << 8);
      int c = idx >> 7, rr = idx & 127;
      ot[(size_t)(n0 + c) * ldoT + i0 + rr] = s_f32[rr * 65 + c];
    }
  }
  if (prm) {  // softmax partials: rows over 64 cols; cols over 128 rows
    if (tid < 128) {
      int r = tid;
      float pm = -1e30f;
#pragma unroll 8
      for (int c = 0; c < 64; c++) pm = fmaxf(pm, s_f32[r * 65 + c]);
      float ps = 0.f;
#pragma unroll 8
      for (int c = 0; c < 64; c++) ps += __expf(s_f32[r * 65 + c] - pm);
      size_t o = (size_t)(b * KN + i0 + r) * gridDim.x + blockIdx.x;
      prm[o] = pm;
      prs[o] = ps;
    } else if (tid < 192) {
      int c = tid - 128;
      float pm = -1e30f;
#pragma unroll 8
      for (int r = 0; r < 128; r++) pm = fmaxf(pm, s_f32[r * 65 + c]);
      float ps = 0.f;
#pragma unroll 8
      for (int r = 0; r < 128; r++) ps += __expf(s_f32[r * 65 + c] - pm);
      size_t o = (size_t)(b * KN + n0 + c) * gridDim.y + blockIdx.y;
      pcm[o] = pm;
      pcs[o] = ps;
    }
  }
  if (pbs && tid < 128) {  // BN partials per output row (channel)
    int r = tid;
    float s = 0.f, s2 = 0.f;
#pragma unroll 8
    for (int c = 0; c < 64; c++) {
      float v = s_f32[r * 65 + c];
      s += v;
      s2 += v * v;
    }
    size_t o = ((size_t)(i0 + r) * KB + b) * gridDim.x + blockIdx.x;
    pbs[o] = s;
    pbs2[o] = s2;
  }
}

// =============================================================================
// transpose: per batch [C][N] -> [N][C]
// =============================================================================
__global__ __launch_bounds__(256) void transpose_kernel(
    const float* __restrict__ in, float* __restrict__ out) {
  __shared__ float t[32][33];
  int b = blockIdx.z;
  const float* ib = in + (size_t)b * KC * KN;
  float* ob = out + (size_t)b * KC * KN;
  int n0 = blockIdx.x * 32, c0 = blockIdx.y * 32;
  int x = threadIdx.x, y = threadIdx.y;
#pragma unroll
  for (int j = 0; j < 4; j++)
    t[y + 8 * j][x] = ib[(size_t)(c0 + y + 8 * j) * KN + n0 + x];
  __syncthreads();
#pragma unroll
  for (int j = 0; j < 4; j++)
    ob[(size_t)(n0 + y + 8 * j) * KC + c0 + x] = t[x][y + 8 * j];
}

// =============================================================================
// combine softmax partials -> rmax/rsum (16 xb), cmax/csum (8 yb)
// =============================================================================
__global__ __launch_bounds__(256) void softmax_combine() {
  int t = blockIdx.x * 256 + threadIdx.x;
  const int total = KB * KN;
  if (t < total) {
    float m = -1e30f;
#pragma unroll
    for (int j = 0; j < 16; j++) m = fmaxf(m, g_prm[t * 16 + j]);
    float s = 0.f;
#pragma unroll
    for (int j = 0; j < 16; j++)
      s += g_prs[t * 16 + j] * __expf(g_prm[t * 16 + j] - m);
    g_rmax[t] = m;
    g_rsum[t] = s;
  } else if (t < 2 * total) {
    int u = t - total;
    float m = -1e30f;
#pragma unroll
    for (int j = 0; j < 8; j++) m = fmaxf(m, g_pcm[u * 8 + j]);
    float s = 0.f;
#pragma unroll
    for (int j = 0; j < 8; j++)
      s += g_pcs[u * 8 + j] * __expf(g_pcm[u * 8 + j] - m);
    g_cmax[u] = m;
    g_csum[u] = s;
  }
}

// =============================================================================
// combine BN partials -> mean/rstd
// =============================================================================
__global__ __launch_bounds__(256) void bnfinal_kernel() {
  int t = blockIdx.x * 256 + threadIdx.x;  // 0..1023 = sel*512 + c
  if (t >= 2 * KC) return;
  float s = 0.f, s2 = 0.f;
  for (int j = 0; j < KB * 16; j++) {
    s += g_pbs[(size_t)t * (KB * 16) + j];
    s2 += g_pbs2[(size_t)t * (KB * 16) + j];
  }
  float m = s / (float)(KB * KN);
  float var = s2 / (float)(KB * KN) - m * m;
  g_mean[t] = m;
  g_rstd[t] = rsqrtf(var + 1e-5f);
}

// =============================================================================
// finalize: Z = (T - mean)*rstd*gamma + beta + X
// =============================================================================
__global__ __launch_bounds__(256) void finalize_kernel(
    const float* __restrict__ X, const float* __restrict__ gamma,
    const float* __restrict__ beta, float* __restrict__ Z, int sel) {
  size_t idx = (size_t)blockIdx.x * 256 + threadIdx.x;
  const float* T = g_t + (size_t)sel * KB * KC * KN;
  int c = (int)((idx >> 10) & (KC - 1));
  float m = g_mean[sel * KC + c];
  float r = g_rstd[sel * KC + c];
  Z[idx] = (T[idx] - m) * r * gamma[c] + beta[c] + X[idx];
}

// =============================================================================
extern "C" void kernel_launch(void* const* d_in, const int* in_sizes, int n_in,
                              void* d_out, int out_size) {
  const float* rgb        = (const float*)d_in[0];
  const float* flow       = (const float*)d_in[1];
  const float* wg_rgb     = (const float*)d_in[2];
  const float* bg_rgb     = (const float*)d_in[3];
  const float* wg_flow    = (const float*)d_in[4];
  const float* bg_flow    = (const float*)d_in[5];
  const float* ww_rgb     = (const float*)d_in[6];
  const float* bw_rgb     = (const float*)d_in[7];
  const float* gamma_rgb  = (const float*)d_in[8];
  const float* beta_rgb   = (const float*)d_in[9];
  const float* ww_flow    = (const float*)d_in[10];
  const float* bw_flow    = (const float*)d_in[11];
  const float* gamma_flow = (const float*)d_in[12];
  const float* beta_flow  = (const float*)d_in[13];
  float* out = (float*)d_out;

  float *p_rgbT, *p_flowT, *p_re, *p_fe, *p_reT, *p_feT, *p_S, *p_S2;
  float *p_rmax, *p_rsum, *p_cmax, *p_csum, *p_yrT, *p_yfT, *p_t;
  float *p_prm, *p_prs, *p_pcm, *p_pcs, *p_pbs, *p_pbs2;
  cudaGetSymbolAddress((void**)&p_rgbT, g_rgbT);
  cudaGetSymbolAddress((void**)&p_flowT, g_flowT);
  cudaGetSymbolAddress((void**)&p_re, g_re);
  cudaGetSymbolAddress((void**)&p_fe, g_fe);
  cudaGetSymbolAddress((void**)&p_reT, g_reT);
  cudaGetSymbolAddress((void**)&p_feT, g_feT);
  cudaGetSymbolAddress((void**)&p_S, g_S);
  cudaGetSymbolAddress((void**)&p_S2, g_S2);
  cudaGetSymbolAddress((void**)&p_rmax, g_rmax);
  cudaGetSymbolAddress((void**)&p_rsum, g_rsum);
  cudaGetSymbolAddress((void**)&p_cmax, g_cmax);
  cudaGetSymbolAddress((void**)&p_csum, g_csum);
  cudaGetSymbolAddress((void**)&p_yrT, g_yrT);
  cudaGetSymbolAddress((void**)&p_yfT, g_yfT);
  cudaGetSymbolAddress((void**)&p_t, g_t);
  cudaGetSymbolAddress((void**)&p_prm, g_prm);
  cudaGetSymbolAddress((void**)&p_prs, g_prs);
  cudaGetSymbolAddress((void**)&p_pcm, g_pcm);
  cudaGetSymbolAddress((void**)&p_pcs, g_pcs);
  cudaGetSymbolAddress((void**)&p_pbs, g_pbs);
  cudaGetSymbolAddress((void**)&p_pbs2, g_pbs2);

  cudaFuncSetAttribute(gemm_tc, cudaFuncAttributeMaxDynamicSharedMemorySize,
                       SMEM_DYN);

  dim3 thr(256);

  // 1) input transposes: [c][n] -> [n][c]
  transpose_kernel<<<dim3(KN / 32, KC / 32, KB), dim3(32, 8)>>>(rgb, p_rgbT);
  transpose_kernel<<<dim3(KN / 32, KC / 32, KB), dim3(32, 8)>>>(flow, p_flowT);

  // 2) embeds: E[i][n] = W @ XT^T ; write normal + transposed
  gemm_tc<<<dim3(16, 2, KB), thr, SMEM_DYN>>>(
      wg_rgb, 0ull, KC, p_rgbT, (unsigned long long)KN * KC, KC,
      nullptr, nullptr, bg_rgb,
      p_re, (unsigned long long)KCI * KN, KN,
      p_reT, (unsigned long long)KN * KCI, KCI,
      nullptr, nullptr, nullptr, nullptr, nullptr, nullptr, KC);
  gemm_tc<<<dim3(16, 2, KB), thr, SMEM_DYN>>>(
      wg_flow, 0ull, KC, p_flowT, (unsigned long long)KN * KC, KC,
      nullptr, nullptr, bg_flow,
      p_fe, (unsigned long long)KCI * KN, KN,
      p_feT, (unsigned long long)KN * KCI, KCI,
      nullptr, nullptr, nullptr, nullptr, nullptr, nullptr, KC);

  // 3) scores: S[n][m] (outN) + S2[m][n] (outT) + softmax partials both ways
  gemm_tc<<<dim3(16, 8, KB), thr, SMEM_DYN>>>(
      p_reT, (unsigned long long)KN * KCI, KCI,
      p_feT, (unsigned long long)KN * KCI, KCI,
      nullptr, nullptr, nullptr,
      p_S, (unsigned long long)KN * KN, KN,
      p_S2, (unsigned long long)KN * KN, KN,
      p_prm, p_prs, p_pcm, p_pcs, nullptr, nullptr, KCI);

  // 4) combine softmax partials
  softmax_combine<<<(2 * KB * KN) / 256, thr>>>();

  // 5) attention applies (exp fused into B staging, 1/sum in epilogue)
  gemm_tc<<<dim3(16, 2, KB), thr, SMEM_DYN>>>(
      p_fe, (unsigned long long)KCI * KN, KN,
      p_S, (unsigned long long)KN * KN, KN,
      p_rmax, p_rsum, nullptr,
      nullptr, 0ull, 0, p_yrT, (unsigned long long)KN * KCI, KCI,
      nullptr, nullptr, nullptr, nullptr, nullptr, nullptr, KN);
  gemm_tc<<<dim3(16, 2, KB), thr, SMEM_DYN>>>(
      p_re, (unsigned long long)KCI * KN, KN,
      p_S2, (unsigned long long)KN * KN, KN,
      p_cmax, p_csum, nullptr,
      nullptr, 0ull, 0, p_yfT, (unsigned long long)KN * KCI, KCI,
      nullptr, nullptr, nullptr, nullptr, nullptr, nullptr, KN);

  // 6) conv2: T[c][n] = W @ YT^T + bias, with BN partial sums
  gemm_tc<<<dim3(16, 4, KB), thr, SMEM_DYN>>>(
      ww_rgb, 0ull, KCI, p_yrT, (unsigned long long)KN * KCI, KCI,
      nullptr, nullptr, bw_rgb,
      p_t, (unsigned long long)KC * KN, KN, nullptr, 0ull, 0,
      nullptr, nullptr, nullptr, nullptr, p_pbs, p_pbs2, KCI);
  gemm_tc<<<dim3(16, 4, KB), thr, SMEM_DYN>>>(
      ww_flow, 0ull, KCI, p_yfT, (unsigned long long)KN * KCI, KCI,
      nullptr, nullptr, bw_flow,
      p_t + (size_t)KB * KC * KN, (unsigned long long)KC * KN, KN,
      nullptr, 0ull, 0,
      nullptr, nullptr, nullptr, nullptr,
      p_pbs + (size_t)KC * KB * 16, p_pbs2 + (size_t)KC * KB * 16, KCI);

  // 7) BN combine + finalize
  bnfinal_kernel<<<4, thr>>>();
  finalize_kernel<<<(KB * KC * KN) / 256, thr>>>(rgb, gamma_rgb, beta_rgb,
                                                 out, 0);
  finalize_kernel<<<(KB * KC * KN) / 256, thr>>>(
      flow, gamma_flow, beta_flow, out + (size_t)KB * KC * KN, 1);
}